// round 2
// baseline (speedup 1.0000x reference)
#include <cuda_runtime.h>

#define NB 4
#define NC 128
#define NN 8192
#define NKN 16

// Scratch (static device allocations — allowed)
__device__ __align__(16) float g_Y[(size_t)NB * NN * 256];  // [b][n][c] c<128: local, c>=128: edge
__device__ float g_sums[640];   // [0:128) sumL [128:256) sumL2 [256:384) sumE [384:512) sumE2 [512:640) cross
__device__ __align__(16) float g_a[256];
__device__ __align__(16) float g_bb[256];

__global__ void zero_sums_kernel() {
    if (threadIdx.x < 640) g_sums[threadIdx.x] = 0.0f;
}

// ---------------------------------------------------------------------------
// K1: Y[b][n][half*128+o] = sum_c W[o][c] * feat[b][c][n]
// Block: 256 threads; tile O=128 (full half) x N=64; K chunked by 16.
// Thread map: lane -> o = lane*4..+3 ; warp -> n-group of 8 (fully coalesced
// float4 output writes along c).
// ---------------------------------------------------------------------------
__global__ void __launch_bounds__(256) gemm_kernel(
    const float* __restrict__ feat, const float* __restrict__ W1,
    const float* __restrict__ W2)
{
    __shared__ float Wsm[16 * 132];  // [kk][o], padded stride 132
    __shared__ float Fs[16 * 64];    // [kk][n]

    const int tid  = threadIdx.x;
    const int b    = blockIdx.z;
    const int half = blockIdx.y;
    const int n0   = blockIdx.x * 64;
    const float* __restrict__ Wg = half ? W2 : W1;

    const int lane = tid & 31;
    const int wrp  = tid >> 5;   // n-group 0..7
    const int r    = tid >> 4;   // Fs row 0..15
    const int cg   = tid & 15;   // Fs col group

    float acc[4][8];
#pragma unroll
    for (int i = 0; i < 4; i++)
#pragma unroll
        for (int j = 0; j < 8; j++) acc[i][j] = 0.0f;

    for (int k0 = 0; k0 < 128; k0 += 16) {
        // stage global reads
        float4 fv = *(const float4*)&feat[((size_t)b * NC + k0 + r) * NN + n0 + cg * 4];
        float wv[8];
#pragma unroll
        for (int it = 0; it < 8; it++) {
            int idx = it * 256 + tid;        // 0..2047
            int o = idx >> 4, kk = idx & 15;
            wv[it] = Wg[o * 128 + k0 + kk];
        }
        __syncthreads();
        *(float4*)&Fs[r * 64 + cg * 4] = fv;
#pragma unroll
        for (int it = 0; it < 8; it++) {
            int idx = it * 256 + tid;
            int o = idx >> 4, kk = idx & 15;
            Wsm[kk * 132 + o] = wv[it];
        }
        __syncthreads();

#pragma unroll
        for (int kk = 0; kk < 16; kk++) {
            float4 w4 = *(const float4*)&Wsm[kk * 132 + lane * 4];
            float4 fa = *(const float4*)&Fs[kk * 64 + wrp * 8];
            float4 fb = *(const float4*)&Fs[kk * 64 + wrp * 8 + 4];
            float w[4] = {w4.x, w4.y, w4.z, w4.w};
            float f[8] = {fa.x, fa.y, fa.z, fa.w, fb.x, fb.y, fb.z, fb.w};
#pragma unroll
            for (int i = 0; i < 4; i++)
#pragma unroll
                for (int j = 0; j < 8; j++)
                    acc[i][j] = fmaf(w[i], f[j], acc[i][j]);
        }
    }

#pragma unroll
    for (int j = 0; j < 8; j++) {
        float4 v = make_float4(acc[0][j], acc[1][j], acc[2][j], acc[3][j]);
        *(float4*)&g_Y[((size_t)(b * NN + n0 + wrp * 8 + j)) * 256 + half * 128 + lane * 4] = v;
    }
}

// ---------------------------------------------------------------------------
// K2: per-channel partial sums via gather. Warp per n (16 n's each), lane owns
// 4 channels (float4 512B coalesced gathers, L2-resident).
// ---------------------------------------------------------------------------
__global__ void __launch_bounds__(256) stats_kernel(const int* __restrict__ knn)
{
    __shared__ float s[640];
    const int tid = threadIdx.x;
    for (int i = tid; i < 640; i += 256) s[i] = 0.0f;
    __syncthreads();

    const int lane = tid & 31, wrp = tid >> 5;
    const int c4 = lane * 4;
    const int base = blockIdx.x * 128 + wrp * 16;  // grid 256 -> covers B*N

    float4 aL  = {0,0,0,0}, aL2 = {0,0,0,0}, aE = {0,0,0,0};
    float4 aE2 = {0,0,0,0}, aX  = {0,0,0,0};

    for (int t = 0; t < 16; t++) {
        const int bn = base + t;
        int my_idx = 0;
        if (lane < 16) my_idx = knn[bn * NKN + lane];
        const float4 l = *(const float4*)&g_Y[(size_t)bn * 256 + c4];
        const int boff = bn & ~(NN - 1);   // b*NN
        float4 S = {0,0,0,0}, Q = {0,0,0,0};
#pragma unroll
        for (int k = 0; k < 16; k++) {
            const int m = __shfl_sync(0xffffffffu, my_idx, k);
            const float4 e = *(const float4*)&g_Y[((size_t)(boff + m)) * 256 + 128 + c4];
            S.x += e.x; S.y += e.y; S.z += e.z; S.w += e.w;
            Q.x = fmaf(e.x, e.x, Q.x); Q.y = fmaf(e.y, e.y, Q.y);
            Q.z = fmaf(e.z, e.z, Q.z); Q.w = fmaf(e.w, e.w, Q.w);
        }
        aE.x += S.x; aE.y += S.y; aE.z += S.z; aE.w += S.w;
        aE2.x += Q.x; aE2.y += Q.y; aE2.z += Q.z; aE2.w += Q.w;
        aX.x = fmaf(S.x, l.x, aX.x); aX.y = fmaf(S.y, l.y, aX.y);
        aX.z = fmaf(S.z, l.z, aX.z); aX.w = fmaf(S.w, l.w, aX.w);
        aL.x += l.x; aL.y += l.y; aL.z += l.z; aL.w += l.w;
        aL2.x = fmaf(l.x, l.x, aL2.x); aL2.y = fmaf(l.y, l.y, aL2.y);
        aL2.z = fmaf(l.z, l.z, aL2.z); aL2.w = fmaf(l.w, l.w, aL2.w);
    }

    atomicAdd(&s[c4 + 0], aL.x);  atomicAdd(&s[c4 + 1], aL.y);
    atomicAdd(&s[c4 + 2], aL.z);  atomicAdd(&s[c4 + 3], aL.w);
    atomicAdd(&s[128 + c4 + 0], aL2.x); atomicAdd(&s[128 + c4 + 1], aL2.y);
    atomicAdd(&s[128 + c4 + 2], aL2.z); atomicAdd(&s[128 + c4 + 3], aL2.w);
    atomicAdd(&s[256 + c4 + 0], aE.x);  atomicAdd(&s[256 + c4 + 1], aE.y);
    atomicAdd(&s[256 + c4 + 2], aE.z);  atomicAdd(&s[256 + c4 + 3], aE.w);
    atomicAdd(&s[384 + c4 + 0], aE2.x); atomicAdd(&s[384 + c4 + 1], aE2.y);
    atomicAdd(&s[384 + c4 + 2], aE2.z); atomicAdd(&s[384 + c4 + 3], aE2.w);
    atomicAdd(&s[512 + c4 + 0], aX.x);  atomicAdd(&s[512 + c4 + 1], aX.y);
    atomicAdd(&s[512 + c4 + 2], aX.z);  atomicAdd(&s[512 + c4 + 3], aX.w);
    __syncthreads();
    for (int i = tid; i < 640; i += 256) atomicAdd(&g_sums[i], s[i]);
}

// ---------------------------------------------------------------------------
// K3: per-channel affine a,b from stats
// ---------------------------------------------------------------------------
__global__ void finalize_kernel(const float* __restrict__ gamma,
                                const float* __restrict__ beta)
{
    const int c = threadIdx.x;  // 0..255
    const float invBN  = 1.0f / (float)(NB * NN);
    const float invBNK = 1.0f / (float)((size_t)NB * NN * NKN);
    float mean, var;
    if (c < 128) {
        float sL = g_sums[c], sL2 = g_sums[128 + c];
        mean = sL * invBN;
        var  = sL2 * invBN - mean * mean;
    } else {
        int cc = c - 128;
        float sL  = g_sums[cc],       sL2 = g_sums[128 + cc];
        float sE  = g_sums[256 + cc], sE2 = g_sums[384 + cc];
        float sX  = g_sums[512 + cc];
        float sD  = sE - (float)NKN * sL;
        float sD2 = sE2 - 2.0f * sX + (float)NKN * sL2;
        mean = sD * invBNK;
        var  = sD2 * invBNK - mean * mean;
    }
    float a = gamma[c] * rsqrtf(var + 1e-5f);
    g_a[c]  = a;
    g_bb[c] = beta[c] - mean * a;
}

// ---------------------------------------------------------------------------
// K4: output. Warp per n (4 n's each), re-gather + ReLU + mean-over-k.
// Stage 256ch x 32n tile in smem (pad 257: conflict-free), write coalesced
// 128B rows to (B, 2O, N).
// ---------------------------------------------------------------------------
__global__ void __launch_bounds__(256) output_kernel(const int* __restrict__ knn,
                                                     float* __restrict__ out)
{
    __shared__ float tile[32 * 257];
    const int tid = threadIdx.x, lane = tid & 31, wrp = tid >> 5;
    const int c4 = lane * 4;
    const int bn0 = blockIdx.x * 32;  // grid 1024

    const float4 a1 = *(const float4*)&g_a[c4];
    const float4 b1 = *(const float4*)&g_bb[c4];
    const float4 a2 = *(const float4*)&g_a[128 + c4];
    const float4 b2 = *(const float4*)&g_bb[128 + c4];

    for (int t = 0; t < 4; t++) {
        const int col = wrp * 4 + t;
        const int bn = bn0 + col;
        int my_idx = 0;
        if (lane < 16) my_idx = knn[bn * NKN + lane];
        const float4 l = *(const float4*)&g_Y[(size_t)bn * 256 + c4];
        const int boff = bn & ~(NN - 1);
        float4 S = {0,0,0,0};
#pragma unroll
        for (int k = 0; k < 16; k++) {
            const int m = __shfl_sync(0xffffffffu, my_idx, k);
            const float4 e = *(const float4*)&g_Y[((size_t)(boff + m)) * 256 + 128 + c4];
            S.x += fmaxf(fmaf(a2.x, e.x - l.x, b2.x), 0.0f);
            S.y += fmaxf(fmaf(a2.y, e.y - l.y, b2.y), 0.0f);
            S.z += fmaxf(fmaf(a2.z, e.z - l.z, b2.z), 0.0f);
            S.w += fmaxf(fmaf(a2.w, e.w - l.w, b2.w), 0.0f);
        }
        tile[col * 257 + c4 + 0] = fmaxf(fmaf(a1.x, l.x, b1.x), 0.0f);
        tile[col * 257 + c4 + 1] = fmaxf(fmaf(a1.y, l.y, b1.y), 0.0f);
        tile[col * 257 + c4 + 2] = fmaxf(fmaf(a1.z, l.z, b1.z), 0.0f);
        tile[col * 257 + c4 + 3] = fmaxf(fmaf(a1.w, l.w, b1.w), 0.0f);
        const float inv = 1.0f / 16.0f;
        tile[col * 257 + 128 + c4 + 0] = S.x * inv;
        tile[col * 257 + 128 + c4 + 1] = S.y * inv;
        tile[col * 257 + 128 + c4 + 2] = S.z * inv;
        tile[col * 257 + 128 + c4 + 3] = S.w * inv;
    }
    __syncthreads();

    const int b = bn0 >> 13;          // NN = 8192
    const int n0 = bn0 & (NN - 1);
#pragma unroll 4
    for (int i = 0; i < 32; i++) {
        int j = i * 256 + tid;
        int row = j >> 5, col = j & 31;
        out[((size_t)(b * 256 + row)) * NN + n0 + col] = tile[col * 257 + row];
    }
}

extern "C" void kernel_launch(void* const* d_in, const int* in_sizes, int n_in,
                              void* d_out, int out_size)
{
    const float* feat  = (const float*)d_in[0];
    const int*   knn   = (const int*)d_in[1];
    const float* W1    = (const float*)d_in[2];
    const float* W2    = (const float*)d_in[3];
    const float* gamma = (const float*)d_in[4];
    const float* beta  = (const float*)d_in[5];
    float* out = (float*)d_out;

    zero_sums_kernel<<<1, 640>>>();
    gemm_kernel<<<dim3(NN / 64, 2, NB), 256>>>(feat, W1, W2);
    stats_kernel<<<256, 256>>>(knn);
    finalize_kernel<<<1, 256>>>(gamma, beta);
    output_kernel<<<1024, 256>>>(knn, out);
}

// round 3
// speedup vs baseline: 1.8888x; 1.8888x over previous
#include <cuda_runtime.h>

#define NB 4
#define NC 128
#define NN 8192
#define NKN 16

typedef unsigned long long u64;

// Scratch (static device allocations — allowed)
__device__ __align__(16) float g_Y[(size_t)NB * NN * 256];  // [b][n][c] c<128: local, c>=128: edge
__device__ float g_sums[640];   // [0:128) sumL [128:256) sumL2 [256:384) sumE [384:512) sumE2 [512:640) cross

__device__ __forceinline__ u64 ff2(u64 a, u64 b, u64 c) {
    u64 d;
    asm("fma.rn.f32x2 %0, %1, %2, %3;" : "=l"(d) : "l"(a), "l"(b), "l"(c));
    return d;
}
__device__ __forceinline__ u64 pk2(float x) {
    u64 r;
    asm("mov.b64 %0, {%1, %1};" : "=l"(r) : "f"(x));
    return r;
}
__device__ __forceinline__ float lo32(u64 v) { return __uint_as_float((unsigned)v); }
__device__ __forceinline__ float hi32(u64 v) { return __uint_as_float((unsigned)(v >> 32)); }

// ---------------------------------------------------------------------------
// K1: Y[b][n][half*128+o] = sum_c W[o][c] * feat[b][c][n]
// Packed f32x2 along n: acc2[4 chan][4 n-pairs] per thread.
// Block(0,0,0) also zeroes g_sums (no other kernel touches it during K1).
// ---------------------------------------------------------------------------
__global__ void __launch_bounds__(256) gemm_kernel(
    const float* __restrict__ feat, const float* __restrict__ W1,
    const float* __restrict__ W2)
{
    __shared__ float Wsm[16 * 132];  // [kk][o], padded stride 132
    __shared__ float Fs[16 * 64];    // [kk][n]

    const int tid  = threadIdx.x;
    const int b    = blockIdx.z;
    const int half = blockIdx.y;
    const int n0   = blockIdx.x * 64;

    if (blockIdx.x == 0 && blockIdx.y == 0 && blockIdx.z == 0) {
        for (int i = tid; i < 640; i += 256) g_sums[i] = 0.0f;
    }

    const float* __restrict__ Wg = half ? W2 : W1;

    const int lane = tid & 31;
    const int wrp  = tid >> 5;   // n-group 0..7
    const int r    = tid >> 4;   // Fs row 0..15
    const int cg   = tid & 15;   // Fs col group

    u64 acc2[4][4];
#pragma unroll
    for (int i = 0; i < 4; i++)
#pragma unroll
        for (int j = 0; j < 4; j++) acc2[i][j] = 0ULL;

    for (int k0 = 0; k0 < 128; k0 += 16) {
        // stage global reads
        float4 fv = *(const float4*)&feat[((size_t)b * NC + k0 + r) * NN + n0 + cg * 4];
        float wv[8];
#pragma unroll
        for (int it = 0; it < 8; it++) {
            int idx = it * 256 + tid;        // 0..2047
            int o = idx >> 4, kk = idx & 15;
            wv[it] = Wg[o * 128 + k0 + kk];
        }
        __syncthreads();
        *(float4*)&Fs[r * 64 + cg * 4] = fv;
#pragma unroll
        for (int it = 0; it < 8; it++) {
            int idx = it * 256 + tid;
            int o = idx >> 4, kk = idx & 15;
            Wsm[kk * 132 + o] = wv[it];
        }
        __syncthreads();

#pragma unroll
        for (int kk = 0; kk < 16; kk++) {
            float4 w4 = *(const float4*)&Wsm[kk * 132 + lane * 4];
            ulonglong2 fa = *(const ulonglong2*)&Fs[kk * 64 + wrp * 8];
            ulonglong2 fb = *(const ulonglong2*)&Fs[kk * 64 + wrp * 8 + 4];
            u64 wp[4] = {pk2(w4.x), pk2(w4.y), pk2(w4.z), pk2(w4.w)};
            u64 f2[4] = {fa.x, fa.y, fb.x, fb.y};
#pragma unroll
            for (int i = 0; i < 4; i++)
#pragma unroll
                for (int j = 0; j < 4; j++)
                    acc2[i][j] = ff2(wp[i], f2[j], acc2[i][j]);
        }
    }

#pragma unroll
    for (int j = 0; j < 4; j++) {
        float4 v0 = make_float4(lo32(acc2[0][j]), lo32(acc2[1][j]),
                                lo32(acc2[2][j]), lo32(acc2[3][j]));
        float4 v1 = make_float4(hi32(acc2[0][j]), hi32(acc2[1][j]),
                                hi32(acc2[2][j]), hi32(acc2[3][j]));
        size_t base = ((size_t)(b * NN + n0 + wrp * 8 + 2 * j)) * 256 + half * 128 + lane * 4;
        *(float4*)&g_Y[base]       = v0;
        *(float4*)&g_Y[base + 256] = v1;
    }
}

// ---------------------------------------------------------------------------
// K2: per-channel partial sums via gather. Grid-stride over bn for perfect
// wave balance (grid 592 = 4 CTAs/SM). Warp per bn, lane owns 4 channels.
// ---------------------------------------------------------------------------
__global__ void __launch_bounds__(256) stats_kernel(const int* __restrict__ knn)
{
    __shared__ float s[640];
    const int tid = threadIdx.x;
    for (int i = tid; i < 640; i += 256) s[i] = 0.0f;
    __syncthreads();

    const int lane = tid & 31, wrp = tid >> 5;
    const int c4 = lane * 4;
    const int stride = gridDim.x * 8;

    float4 aL  = {0,0,0,0}, aL2 = {0,0,0,0}, aE = {0,0,0,0};
    float4 aE2 = {0,0,0,0}, aX  = {0,0,0,0};

    for (int bn = blockIdx.x * 8 + wrp; bn < NB * NN; bn += stride) {
        int my_idx = 0;
        if (lane < 16) my_idx = knn[bn * NKN + lane];
        const float4 l = *(const float4*)&g_Y[(size_t)bn * 256 + c4];
        const int boff = bn & ~(NN - 1);   // b*NN
        float4 S = {0,0,0,0}, Q = {0,0,0,0};
#pragma unroll
        for (int k = 0; k < 16; k++) {
            const int m = __shfl_sync(0xffffffffu, my_idx, k);
            const float4 e = *(const float4*)&g_Y[((size_t)(boff + m)) * 256 + 128 + c4];
            S.x += e.x; S.y += e.y; S.z += e.z; S.w += e.w;
            Q.x = fmaf(e.x, e.x, Q.x); Q.y = fmaf(e.y, e.y, Q.y);
            Q.z = fmaf(e.z, e.z, Q.z); Q.w = fmaf(e.w, e.w, Q.w);
        }
        aE.x += S.x; aE.y += S.y; aE.z += S.z; aE.w += S.w;
        aE2.x += Q.x; aE2.y += Q.y; aE2.z += Q.z; aE2.w += Q.w;
        aX.x = fmaf(S.x, l.x, aX.x); aX.y = fmaf(S.y, l.y, aX.y);
        aX.z = fmaf(S.z, l.z, aX.z); aX.w = fmaf(S.w, l.w, aX.w);
        aL.x += l.x; aL.y += l.y; aL.z += l.z; aL.w += l.w;
        aL2.x = fmaf(l.x, l.x, aL2.x); aL2.y = fmaf(l.y, l.y, aL2.y);
        aL2.z = fmaf(l.z, l.z, aL2.z); aL2.w = fmaf(l.w, l.w, aL2.w);
    }

    atomicAdd(&s[c4 + 0], aL.x);  atomicAdd(&s[c4 + 1], aL.y);
    atomicAdd(&s[c4 + 2], aL.z);  atomicAdd(&s[c4 + 3], aL.w);
    atomicAdd(&s[128 + c4 + 0], aL2.x); atomicAdd(&s[128 + c4 + 1], aL2.y);
    atomicAdd(&s[128 + c4 + 2], aL2.z); atomicAdd(&s[128 + c4 + 3], aL2.w);
    atomicAdd(&s[256 + c4 + 0], aE.x);  atomicAdd(&s[256 + c4 + 1], aE.y);
    atomicAdd(&s[256 + c4 + 2], aE.z);  atomicAdd(&s[256 + c4 + 3], aE.w);
    atomicAdd(&s[384 + c4 + 0], aE2.x); atomicAdd(&s[384 + c4 + 1], aE2.y);
    atomicAdd(&s[384 + c4 + 2], aE2.z); atomicAdd(&s[384 + c4 + 3], aE2.w);
    atomicAdd(&s[512 + c4 + 0], aX.x);  atomicAdd(&s[512 + c4 + 1], aX.y);
    atomicAdd(&s[512 + c4 + 2], aX.z);  atomicAdd(&s[512 + c4 + 3], aX.w);
    __syncthreads();
    for (int i = tid; i < 640; i += 256) atomicAdd(&g_sums[i], s[i]);
}

// ---------------------------------------------------------------------------
// K3: output. Finalize (stats -> per-channel a,b) replicated per block into
// smem, then re-gather + ReLU + mean-over-k; smem tile -> coalesced writes.
// ---------------------------------------------------------------------------
__global__ void __launch_bounds__(256) output_kernel(const int* __restrict__ knn,
                                                     const float* __restrict__ gamma,
                                                     const float* __restrict__ beta,
                                                     float* __restrict__ out)
{
    __shared__ float tile[32 * 257];
    __shared__ float sa[256], sb[256];
    const int tid = threadIdx.x, lane = tid & 31, wrp = tid >> 5;
    const int c4 = lane * 4;
    const int bn0 = blockIdx.x * 32;  // grid 1024

    // replicated finalize: per-channel affine from global stats
    {
        const int c = tid;  // 0..255
        const float invBN  = 1.0f / (float)(NB * NN);
        const float invBNK = 1.0f / (float)((size_t)NB * NN * NKN);
        float mean, var;
        if (c < 128) {
            float sL = g_sums[c], sL2 = g_sums[128 + c];
            mean = sL * invBN;
            var  = sL2 * invBN - mean * mean;
        } else {
            int cc = c - 128;
            float sL  = g_sums[cc],       sL2 = g_sums[128 + cc];
            float sE  = g_sums[256 + cc], sE2 = g_sums[384 + cc];
            float sX  = g_sums[512 + cc];
            float sD  = sE - (float)NKN * sL;
            float sD2 = sE2 - 2.0f * sX + (float)NKN * sL2;
            mean = sD * invBNK;
            var  = sD2 * invBNK - mean * mean;
        }
        float a = gamma[c] * rsqrtf(var + 1e-5f);
        sa[c] = a;
        sb[c] = beta[c] - mean * a;
    }
    __syncthreads();

    const float4 a1 = *(const float4*)&sa[c4];
    const float4 b1 = *(const float4*)&sb[c4];
    const float4 a2 = *(const float4*)&sa[128 + c4];
    const float4 b2 = *(const float4*)&sb[128 + c4];

    for (int t = 0; t < 4; t++) {
        const int col = wrp * 4 + t;
        const int bn = bn0 + col;
        int my_idx = 0;
        if (lane < 16) my_idx = knn[bn * NKN + lane];
        const float4 l = *(const float4*)&g_Y[(size_t)bn * 256 + c4];
        const int boff = bn & ~(NN - 1);
        float4 S = {0,0,0,0};
#pragma unroll
        for (int k = 0; k < 16; k++) {
            const int m = __shfl_sync(0xffffffffu, my_idx, k);
            const float4 e = *(const float4*)&g_Y[((size_t)(boff + m)) * 256 + 128 + c4];
            S.x += fmaxf(fmaf(a2.x, e.x - l.x, b2.x), 0.0f);
            S.y += fmaxf(fmaf(a2.y, e.y - l.y, b2.y), 0.0f);
            S.z += fmaxf(fmaf(a2.z, e.z - l.z, b2.z), 0.0f);
            S.w += fmaxf(fmaf(a2.w, e.w - l.w, b2.w), 0.0f);
        }
        tile[col * 257 + c4 + 0] = fmaxf(fmaf(a1.x, l.x, b1.x), 0.0f);
        tile[col * 257 + c4 + 1] = fmaxf(fmaf(a1.y, l.y, b1.y), 0.0f);
        tile[col * 257 + c4 + 2] = fmaxf(fmaf(a1.z, l.z, b1.z), 0.0f);
        tile[col * 257 + c4 + 3] = fmaxf(fmaf(a1.w, l.w, b1.w), 0.0f);
        const float inv = 1.0f / 16.0f;
        tile[col * 257 + 128 + c4 + 0] = S.x * inv;
        tile[col * 257 + 128 + c4 + 1] = S.y * inv;
        tile[col * 257 + 128 + c4 + 2] = S.z * inv;
        tile[col * 257 + 128 + c4 + 3] = S.w * inv;
    }
    __syncthreads();

    const int b = bn0 >> 13;          // NN = 8192
    const int n0 = bn0 & (NN - 1);
#pragma unroll 4
    for (int i = 0; i < 32; i++) {
        int j = i * 256 + tid;
        int row = j >> 5, col = j & 31;
        out[((size_t)(b * 256 + row)) * NN + n0 + col] = tile[col * 257 + row];
    }
}

extern "C" void kernel_launch(void* const* d_in, const int* in_sizes, int n_in,
                              void* d_out, int out_size)
{
    const float* feat  = (const float*)d_in[0];
    const int*   knn   = (const int*)d_in[1];
    const float* W1    = (const float*)d_in[2];
    const float* W2    = (const float*)d_in[3];
    const float* gamma = (const float*)d_in[4];
    const float* beta  = (const float*)d_in[5];
    float* out = (float*)d_out;

    gemm_kernel<<<dim3(NN / 64, 2, NB), 256>>>(feat, W1, W2);
    stats_kernel<<<592, 256>>>(knn);
    output_kernel<<<1024, 256>>>(knn, gamma, beta, out);
}